// round 13
// baseline (speedup 1.0000x reference)
#include <cuda_runtime.h>

#define NEG 0.2f

// Scratch (__device__ globals; no allocation allowed)
__device__ float          gH[8 * 1024 * 128];     // projected features (4 MB)
__device__ float2         gE[32 * 1024];          // (e1,e2) sorted order
__device__ unsigned short gPerm[32 * 1024];
__device__ int            gStarts[32 * 1026];     // bucket starts
__device__ float2         gQC[32 * 1024];         // per-query (c1,c2), bucket order
__device__ unsigned short gQOut[32 * 1024];       // original query idx, bucket order
__device__ float2         gTot[32 * 32 * 32];     // per-(bh,seg,lane) totals (t1,t2)

struct ScalS {
    float          ws[128], wd[128];
    float          sS[1024];
    float          dvA[1024], dvB[1024];
    float2         pe[1024];
    float2         wsum2[32];
    unsigned short pmA[1024], pmB[1024];
    int            wsumI[32];
    int            cnt[1025];
    int            starts[1026];
};

__device__ __forceinline__ void shfl_pass(float& v, int& idx, int j, int k, int tid) {
    float pv = __shfl_xor_sync(0xFFFFFFFFu, v, j);
    int   pi = __shfl_xor_sync(0xFFFFFFFFu, idx, j);
    bool  up   = ((tid & k) == 0);
    bool  iLow = ((tid & j) == 0);
    float lo = iLow ? v : pv, hi = iLow ? pv : v;
    bool  sw = up ? (lo > hi) : (lo < hi);
    if (sw) { v = pv; idx = pi; }
}

// ---------------------------------------------------------------------------
// GEMM: h = x @ W (8192x128 @ 128x128). 64x64 tile, 256 thr, 4x4/thread.
// Runs on a forked stream, concurrent with scalK. Grid (128, 2) = 256 blocks.
// ---------------------------------------------------------------------------
__global__ __launch_bounds__(256) void gemm_kernel(const float* __restrict__ A,
                                                   const float* __restrict__ W) {
    __shared__ float As[16][64];
    __shared__ float Bs[16][64];
    const int bm = blockIdx.x * 64, bn = blockIdx.y * 64;
    const int tid = threadIdx.x, tr = tid >> 4, tc = tid & 15;

    float acc[4][4];
#pragma unroll
    for (int i = 0; i < 4; i++)
#pragma unroll
        for (int j = 0; j < 4; j++) acc[i][j] = 0.f;

    for (int k0 = 0; k0 < 128; k0 += 16) {
#pragma unroll 4
        for (int i = tid; i < 1024; i += 256) {
            int m = i >> 4, kk = i & 15;
            As[kk][m] = A[(size_t)(bm + m) * 128 + k0 + kk];
        }
#pragma unroll 4
        for (int i = tid; i < 1024; i += 256) {
            int kk = i >> 6, n = i & 63;
            Bs[kk][n] = W[(size_t)(k0 + kk) * 128 + bn + n];
        }
        __syncthreads();
#pragma unroll
        for (int kk = 0; kk < 16; kk++) {
            float a[4], b[4];
#pragma unroll
            for (int i = 0; i < 4; i++) a[i] = As[kk][tr * 4 + i];
#pragma unroll
            for (int j = 0; j < 4; j++) b[j] = Bs[kk][tc * 4 + j];
#pragma unroll
            for (int i = 0; i < 4; i++)
#pragma unroll
                for (int j = 0; j < 4; j++) acc[i][j] = fmaf(a[i], b[j], acc[i][j]);
        }
        __syncthreads();
    }
#pragma unroll
    for (int i = 0; i < 4; i++)
        *reinterpret_cast<float4*>(&gH[(size_t)(bm + tr * 4 + i) * 128 + bn + tc * 4]) =
            make_float4(acc[i][0], acc[i][1], acc[i][2], acc[i][3]);
}

// ---------------------------------------------------------------------------
// scalK: scalar phase per (b,h). Independent of the GEMM (dots come from x
// via projected vectors ws/wd). 32 blocks x 1024 threads.
// ---------------------------------------------------------------------------
__global__ __launch_bounds__(1024) void scalK(const float* __restrict__ x,
                                              const float* __restrict__ W,
                                              const float* __restrict__ a_src,
                                              const float* __restrict__ a_dst) {
    extern __shared__ char sraw[];
    ScalS& S = *reinterpret_cast<ScalS*>(sraw);
    const int bh = blockIdx.x, b = bh >> 2, head = bh & 3;
    const int tid = threadIdx.x, lane = tid & 31, wid = tid >> 5;

    // --- projected attention vectors: ws = W[:,head]·a_src, wd likewise ---
    {
        int k = tid >> 3, c8 = tid & 7;
        float4 wv  = *reinterpret_cast<const float4*>(W + (size_t)k * 128 + head * 32 + c8 * 4);
        float4 as4 = *reinterpret_cast<const float4*>(a_src + head * 32 + c8 * 4);
        float4 ad4 = *reinterpret_cast<const float4*>(a_dst + head * 32 + c8 * 4);
        float ps = wv.x * as4.x + wv.y * as4.y + wv.z * as4.z + wv.w * as4.w;
        float pd = wv.x * ad4.x + wv.y * ad4.y + wv.z * ad4.z + wv.w * ad4.w;
#pragma unroll
        for (int o = 4; o >= 1; o >>= 1) {
            ps += __shfl_xor_sync(0xFFFFFFFFu, ps, o);
            pd += __shfl_xor_sync(0xFFFFFFFFu, pd, o);
        }
        if (c8 == 0) { S.ws[k] = ps; S.wd[k] = pd; }
    }
    __syncthreads();

    // --- dots from x: warp wid handles rows wid*32..+31 ---
    {
        float4 wsv = reinterpret_cast<float4*>(S.ws)[lane];
        float4 wdv = reinterpret_cast<float4*>(S.wd)[lane];
        const float4* xb = reinterpret_cast<const float4*>(x + (size_t)b * 1024 * 128);
        for (int jj = 0; jj < 32; jj++) {
            int row = wid * 32 + jj;
            float4 xv = xb[row * 32 + lane];
            float pd = xv.x * wdv.x + xv.y * wdv.y + xv.z * wdv.z + xv.w * wdv.w;
            float ps = xv.x * wsv.x + xv.y * wsv.y + xv.z * wsv.z + xv.w * wsv.w;
#pragma unroll
            for (int o = 16; o >= 1; o >>= 1) {
                pd += __shfl_xor_sync(0xFFFFFFFFu, pd, o);
                ps += __shfl_xor_sync(0xFFFFFFFFu, ps, o);
            }
            if (lane == 0) { S.dvA[row] = pd; S.sS[row] = ps; }
        }
    }
    __syncthreads();

    float v   = S.dvA[tid];
    float s   = S.sS[tid];
    int   idx = tid;

    // --- bitonic sort: k=2..32 in registers (shfl) ---
#pragma unroll
    for (int k = 2; k <= 32; k <<= 1)
#pragma unroll
        for (int j = k >> 1; j >= 1; j >>= 1) shfl_pass(v, idx, j, k, tid);

    float*          dvc = S.dvA;  float*          dvn = S.dvB;
    unsigned short* pmc = S.pmA;  unsigned short* pmn = S.pmB;
    dvc[tid] = v; pmc[tid] = (unsigned short)idx;
    __syncthreads();

    // --- k=64..1024: ping-pong cross-warp passes + shfl tails ---
    for (int k = 64; k <= 1024; k <<= 1) {
        for (int j = k >> 1; j >= 32; j >>= 1) {
            float          v0 = dvc[tid];
            unsigned short i0 = pmc[tid];
            float          pv = dvc[tid ^ j];
            unsigned short pi = pmc[tid ^ j];
            bool  up   = ((tid & k) == 0);
            bool  iLow = ((tid & j) == 0);
            float lo = iLow ? v0 : pv, hi = iLow ? pv : v0;
            bool  sw = up ? (lo > hi) : (lo < hi);
            dvn[tid] = sw ? pv : v0;
            pmn[tid] = sw ? pi : i0;
            __syncthreads();
            float* tf = dvc; dvc = dvn; dvn = tf;
            unsigned short* tp = pmc; pmc = pmn; pmn = tp;
        }
        v = dvc[tid]; idx = pmc[tid];
#pragma unroll
        for (int j = 16; j >= 1; j >>= 1) shfl_pass(v, idx, j, k, tid);
        dvc[tid] = v; pmc[tid] = (unsigned short)idx;
        __syncthreads();
    }
    const float*          dvf = dvc;
    const unsigned short* pmf = pmc;

    // --- exps ---
    const float dmax = dvf[1023];
    float  xx = v - dmax;
    float2 ev = make_float2(__expf(xx), __expf(NEG * xx));
    gE[bh * 1024 + tid]    = ev;
    gPerm[bh * 1024 + tid] = pmf[tid];

    // --- fused inclusive block scan of (e1, e2) ---
    {
        float2 sv = ev;
#pragma unroll
        for (int off = 1; off < 32; off <<= 1) {
            float nx = __shfl_up_sync(0xFFFFFFFFu, sv.x, off);
            float ny = __shfl_up_sync(0xFFFFFFFFu, sv.y, off);
            if (lane >= off) { sv.x += nx; sv.y += ny; }
        }
        if (lane == 31) S.wsum2[wid] = sv;
        __syncthreads();
        if (wid == 0) {
            float2 w = S.wsum2[lane];
#pragma unroll
            for (int off = 1; off < 32; off <<= 1) {
                float nx = __shfl_up_sync(0xFFFFFFFFu, w.x, off);
                float ny = __shfl_up_sync(0xFFFFFFFFu, w.y, off);
                if (lane >= off) { w.x += nx; w.y += ny; }
            }
            S.wsum2[lane] = w;
        }
        __syncthreads();
        if (wid) { float2 c = S.wsum2[wid - 1]; sv.x += c.x; sv.y += c.y; }
        S.pe[tid] = sv;
        __syncthreads();
    }

    // --- binary search + per-query coefficients ---
    float c1c, c2c;
    int   kk;
    {
        const float T1 = S.pe[1023].x;
        float key = -s;
        int   k   = 0;
#pragma unroll
        for (int step = 1024; step >= 1; step >>= 1) {
            int nk = k + step;
            if (nk <= 1024 && dvf[nk - 1] < key) k = nk;
        }
        kk = k;
        float u  = s + dmax;
        float m  = fmaxf(u, NEG * u);
        float w1 = __expf(u - m);
        float w2 = __expf(NEG * u - m);
        float2 P = (k > 0) ? S.pe[k - 1] : make_float2(0.f, 0.f);
        float den = fmaf(w1, T1 - P.x, w2 * P.y);
        float inv = 1.f / den;
        c1c = w1 * inv;
        c2c = w2 * inv;
    }

    // --- counting sort of queries by bucket = k ---
    for (int i = tid; i < 1025; i += 1024) S.cnt[i] = 0;
    __syncthreads();
    atomicAdd(&S.cnt[kk], 1);
    __syncthreads();
    {
        int cv = S.cnt[tid];
#pragma unroll
        for (int off = 1; off < 32; off <<= 1) {
            int n = __shfl_up_sync(0xFFFFFFFFu, cv, off);
            if (lane >= off) cv += n;
        }
        if (lane == 31) S.wsumI[wid] = cv;
        __syncthreads();
        if (wid == 0) {
            int w = S.wsumI[lane];
#pragma unroll
            for (int off = 1; off < 32; off <<= 1) {
                int n = __shfl_up_sync(0xFFFFFFFFu, w, off);
                if (lane >= off) w += n;
            }
            S.wsumI[lane] = w;
        }
        __syncthreads();
        S.starts[tid + 1] = cv + (wid ? S.wsumI[wid - 1] : 0);
        if (tid == 0) S.starts[0] = 0;
        __syncthreads();
        if (tid == 0) S.starts[1025] = S.starts[1024] + S.cnt[1024];
        __syncthreads();
    }
    for (int i = tid; i < 1025; i += 1024) S.cnt[i] = 0;
    __syncthreads();
    {
        int pos = S.starts[kk] + atomicAdd(&S.cnt[kk], 1);
        gQC[bh * 1024 + pos]   = make_float2(c1c, c2c);
        gQOut[bh * 1024 + pos] = (unsigned short)tid;
    }
    for (int i = tid; i < 1026; i += 1024) gStarts[bh * 1026 + i] = S.starts[i];
}

// ---------------------------------------------------------------------------
// vecB1: segment totals, wide. Grid (32 bh, 4) x 256. Warp = one segment.
// ---------------------------------------------------------------------------
__global__ __launch_bounds__(256) void vecB1() {
    __shared__ unsigned short sPm[256];
    __shared__ float2         sE[256];

    const int bh = blockIdx.x, y = blockIdx.y;
    const int b = bh >> 2, head = bh & 3;
    const int tid = threadIdx.x, lane = tid & 31, wid = tid >> 5;
    const int base = bh * 1024 + y * 256;

    sPm[tid] = gPerm[base + tid];
    sE[tid]  = gE[base + tid];
    __syncthreads();

    const float* hhead = gH + (size_t)b * 1024 * 128 + head * 32;
    const int j0 = wid * 32;
    float t1 = 0.f, t2 = 0.f;
#pragma unroll
    for (int jj = 0; jj < 32; jj++) {
        float  hv = hhead[(size_t)sPm[j0 + jj] * 128 + lane];
        float2 ee = sE[j0 + jj];
        t1 = fmaf(ee.x, hv, t1);
        t2 = fmaf(ee.y, hv, t2);
    }
    gTot[(bh * 32 + y * 8 + wid) * 32 + lane] = make_float2(t1, t2);
}

// ---------------------------------------------------------------------------
// vecB2e: merge-emit, wide. Grid (32 bh, 4) x 256. Warp = one emit segment.
// ---------------------------------------------------------------------------
__global__ __launch_bounds__(256) void vecB2e(float* __restrict__ out) {
    __shared__ float2         sTot[32][32];
    __shared__ unsigned short sPm[256];
    __shared__ float2         sE[256];
    __shared__ int            sStarts[258];
    __shared__ float2         sQc[1024];
    __shared__ unsigned short sQo[1024];

    const int bh = blockIdx.x, y = blockIdx.y;
    const int b = bh >> 2, head = bh & 3;
    const int tid = threadIdx.x, lane = tid & 31, wid = tid >> 5;
    const int base = bh * 1024 + y * 256;

    for (int i = tid; i < 1024; i += 256) sTot[i >> 5][i & 31] = gTot[bh * 1024 + i];
    sPm[tid] = gPerm[base + tid];
    sE[tid]  = gE[base + tid];
    for (int i = tid; i < 258; i += 256) sStarts[i] = gStarts[bh * 1026 + y * 256 + i];
    __syncthreads();

    const int q0   = sStarts[0];
    const int qEnd = (y == 3) ? sStarts[257] : sStarts[256];
    for (int t = tid; t < qEnd - q0; t += 256) {
        sQc[t] = gQC[bh * 1024 + q0 + t];
        sQo[t] = gQOut[bh * 1024 + q0 + t];
    }
    __syncthreads();

    const int emitSeg = y * 8 + wid;
    float tv1 = 0.f, off1 = 0.f, off2 = 0.f;
#pragma unroll
    for (int t = 0; t < 32; t++) {
        float2 tt = sTot[t][lane];
        tv1 += tt.x;
        if (t < emitSeg) { off1 += tt.x; off2 += tt.y; }
    }

    const float* hhead = gH + (size_t)b * 1024 * 128 + head * 32;
    const int    j0    = wid * 32;
    float hv[32];
#pragma unroll
    for (int jj = 0; jj < 32; jj++)
        hv[jj] = hhead[(size_t)sPm[j0 + jj] * 128 + lane];

    float acc1 = off1, acc2 = off2;
    int    qp = sStarts[j0];
    float* ob = out + (size_t)(b * 1024) * 128 + head * 32 + lane;

#pragma unroll
    for (int jj = 0; jj < 32; jj++) {
        int qe = sStarts[j0 + jj + 1];
        while (qp < qe) {
            float2 cc = sQc[qp - q0];
            int    i  = sQo[qp - q0];
            ob[(size_t)i * 128] = fmaf(cc.x, tv1 - acc1, cc.y * acc2);
            qp++;
        }
        float2 ee = sE[j0 + jj];
        acc1 = fmaf(ee.x, hv[jj], acc1);
        acc2 = fmaf(ee.y, hv[jj], acc2);
    }
    if (emitSeg == 31) {
        int qT = sStarts[257];
        while (qp < qT) {
            float2 cc = sQc[qp - q0];
            int    i  = sQo[qp - q0];
            ob[(size_t)i * 128] = fmaf(cc.x, tv1 - acc1, cc.y * acc2);
            qp++;
        }
    }
}

// ---------------------------------------------------------------------------
// Launch: fork gemm onto a side stream so it runs concurrently with scalK
// (they are independent), join, then the two wide vector kernels.
// Stream/events created once (host-side only; no device allocation).
// ---------------------------------------------------------------------------
extern "C" void kernel_launch(void* const* d_in, const int* in_sizes, int n_in,
                              void* d_out, int out_size) {
    const float* x     = (const float*)d_in[0];
    const float* W     = (const float*)d_in[1];
    const float* a_src = (const float*)d_in[2];
    const float* a_dst = (const float*)d_in[3];
    float*       out   = (float*)d_out;

    static cudaStream_t s2 = nullptr;
    static cudaEvent_t  evFork, evJoin;
    static int inited = 0;
    if (!inited) {
        cudaStreamCreateWithFlags(&s2, cudaStreamNonBlocking);
        cudaEventCreateWithFlags(&evFork, cudaEventDisableTiming);
        cudaEventCreateWithFlags(&evJoin, cudaEventDisableTiming);
        cudaFuncSetAttribute(scalK, cudaFuncAttributeMaxDynamicSharedMemorySize,
                             (int)sizeof(ScalS));
        inited = 1;
    }

    // fork: gemm runs on s2 concurrently with scalK on the main stream
    cudaEventRecord(evFork, 0);
    cudaStreamWaitEvent(s2, evFork, 0);
    gemm_kernel<<<dim3(128, 2), 256, 0, s2>>>(x, W);
    scalK<<<32, 1024, sizeof(ScalS)>>>(x, W, a_src, a_dst);
    // join: vector phase needs both gH (gemm) and the scalar outputs
    cudaEventRecord(evJoin, s2);
    cudaStreamWaitEvent(0, evJoin, 0);

    vecB1<<<dim3(32, 4), 256>>>();
    vecB2e<<<dim3(32, 4), 256>>>(out);
}

// round 15
// speedup vs baseline: 1.0709x; 1.0709x over previous
#include <cuda_runtime.h>
#include <cstdint>

#define NEG 0.2f

// Scratch (__device__ globals; no allocation allowed)
__device__ float          gH[8 * 1024 * 128];     // projected features (4 MB)
__device__ float2         gE[32 * 1024];          // (e1,e2) sorted order
__device__ unsigned short gPerm[32 * 1024];
__device__ int            gStarts[32 * 1026];     // bucket starts
__device__ float2         gQC[32 * 1024];         // per-query (c1,c2), bucket order
__device__ unsigned short gQOut[32 * 1024];       // original query idx, bucket order

struct ScalS {
    float          ws[128], wd[128];
    float          sS[1024];
    float          dvA[1024], dvB[1024];
    float2         pe[1024];
    float2         wsum2[32];
    unsigned short pmA[1024], pmB[1024];
    int            wsumI[32];
    int            cnt[1025];
    int            starts[1026];
};

__device__ __forceinline__ void shfl_pass(float& v, int& idx, int j, int k, int tid) {
    float pv = __shfl_xor_sync(0xFFFFFFFFu, v, j);
    int   pi = __shfl_xor_sync(0xFFFFFFFFu, idx, j);
    bool  up   = ((tid & k) == 0);
    bool  iLow = ((tid & j) == 0);
    float lo = iLow ? v : pv, hi = iLow ? pv : v;
    bool  sw = up ? (lo > hi) : (lo < hi);
    if (sw) { v = pv; idx = pi; }
}

__device__ __forceinline__ uint32_t smem_u32(const void* p) {
    uint32_t a;
    asm("{ .reg .u64 t; cvta.to.shared.u64 t, %1; cvt.u32.u64 %0, t; }" : "=r"(a) : "l"(p));
    return a;
}

// ---------------------------------------------------------------------------
// GEMM: h = x @ W (8192x128 @ 128x128). 64x64 tile, 256 thr, 4x4/thread.
// Runs on a forked stream, concurrent with scalK. Grid (128, 2) = 256 blocks.
// ---------------------------------------------------------------------------
__global__ __launch_bounds__(256) void gemm_kernel(const float* __restrict__ A,
                                                   const float* __restrict__ W) {
    __shared__ float As[16][64];
    __shared__ float Bs[16][64];
    const int bm = blockIdx.x * 64, bn = blockIdx.y * 64;
    const int tid = threadIdx.x, tr = tid >> 4, tc = tid & 15;

    float acc[4][4];
#pragma unroll
    for (int i = 0; i < 4; i++)
#pragma unroll
        for (int j = 0; j < 4; j++) acc[i][j] = 0.f;

    for (int k0 = 0; k0 < 128; k0 += 16) {
#pragma unroll 4
        for (int i = tid; i < 1024; i += 256) {
            int m = i >> 4, kk = i & 15;
            As[kk][m] = A[(size_t)(bm + m) * 128 + k0 + kk];
        }
#pragma unroll 4
        for (int i = tid; i < 1024; i += 256) {
            int kk = i >> 6, n = i & 63;
            Bs[kk][n] = W[(size_t)(k0 + kk) * 128 + bn + n];
        }
        __syncthreads();
#pragma unroll
        for (int kk = 0; kk < 16; kk++) {
            float a[4], b[4];
#pragma unroll
            for (int i = 0; i < 4; i++) a[i] = As[kk][tr * 4 + i];
#pragma unroll
            for (int j = 0; j < 4; j++) b[j] = Bs[kk][tc * 4 + j];
#pragma unroll
            for (int i = 0; i < 4; i++)
#pragma unroll
                for (int j = 0; j < 4; j++) acc[i][j] = fmaf(a[i], b[j], acc[i][j]);
        }
        __syncthreads();
    }
#pragma unroll
    for (int i = 0; i < 4; i++)
        *reinterpret_cast<float4*>(&gH[(size_t)(bm + tr * 4 + i) * 128 + bn + tc * 4]) =
            make_float4(acc[i][0], acc[i][1], acc[i][2], acc[i][3]);
}

// ---------------------------------------------------------------------------
// scalK: scalar phase per (b,h). Independent of the GEMM (dots come from x
// via projected vectors ws/wd). 32 blocks x 1024 threads.
// ---------------------------------------------------------------------------
__global__ __launch_bounds__(1024) void scalK(const float* __restrict__ x,
                                              const float* __restrict__ W,
                                              const float* __restrict__ a_src,
                                              const float* __restrict__ a_dst) {
    extern __shared__ char sraw[];
    ScalS& S = *reinterpret_cast<ScalS*>(sraw);
    const int bh = blockIdx.x, b = bh >> 2, head = bh & 3;
    const int tid = threadIdx.x, lane = tid & 31, wid = tid >> 5;

    // --- projected attention vectors: ws = W[:,head]·a_src, wd likewise ---
    {
        int k = tid >> 3, c8 = tid & 7;
        float4 wv  = *reinterpret_cast<const float4*>(W + (size_t)k * 128 + head * 32 + c8 * 4);
        float4 as4 = *reinterpret_cast<const float4*>(a_src + head * 32 + c8 * 4);
        float4 ad4 = *reinterpret_cast<const float4*>(a_dst + head * 32 + c8 * 4);
        float ps = wv.x * as4.x + wv.y * as4.y + wv.z * as4.z + wv.w * as4.w;
        float pd = wv.x * ad4.x + wv.y * ad4.y + wv.z * ad4.z + wv.w * ad4.w;
#pragma unroll
        for (int o = 4; o >= 1; o >>= 1) {
            ps += __shfl_xor_sync(0xFFFFFFFFu, ps, o);
            pd += __shfl_xor_sync(0xFFFFFFFFu, pd, o);
        }
        if (c8 == 0) { S.ws[k] = ps; S.wd[k] = pd; }
    }
    __syncthreads();

    // --- dots from x: warp wid handles rows wid*32..+31 ---
    {
        float4 wsv = reinterpret_cast<float4*>(S.ws)[lane];
        float4 wdv = reinterpret_cast<float4*>(S.wd)[lane];
        const float4* xb = reinterpret_cast<const float4*>(x + (size_t)b * 1024 * 128);
        for (int jj = 0; jj < 32; jj++) {
            int row = wid * 32 + jj;
            float4 xv = xb[row * 32 + lane];
            float pd = xv.x * wdv.x + xv.y * wdv.y + xv.z * wdv.z + xv.w * wdv.w;
            float ps = xv.x * wsv.x + xv.y * wsv.y + xv.z * wsv.z + xv.w * wsv.w;
#pragma unroll
            for (int o = 16; o >= 1; o >>= 1) {
                pd += __shfl_xor_sync(0xFFFFFFFFu, pd, o);
                ps += __shfl_xor_sync(0xFFFFFFFFu, ps, o);
            }
            if (lane == 0) { S.dvA[row] = pd; S.sS[row] = ps; }
        }
    }
    __syncthreads();

    float v   = S.dvA[tid];
    float s   = S.sS[tid];
    int   idx = tid;

    // --- bitonic sort: k=2..32 in registers (shfl) ---
#pragma unroll
    for (int k = 2; k <= 32; k <<= 1)
#pragma unroll
        for (int j = k >> 1; j >= 1; j >>= 1) shfl_pass(v, idx, j, k, tid);

    float*          dvc = S.dvA;  float*          dvn = S.dvB;
    unsigned short* pmc = S.pmA;  unsigned short* pmn = S.pmB;
    dvc[tid] = v; pmc[tid] = (unsigned short)idx;
    __syncthreads();

    // --- k=64..1024: ping-pong cross-warp passes + shfl tails ---
    for (int k = 64; k <= 1024; k <<= 1) {
        for (int j = k >> 1; j >= 32; j >>= 1) {
            float          v0 = dvc[tid];
            unsigned short i0 = pmc[tid];
            float          pv = dvc[tid ^ j];
            unsigned short pi = pmc[tid ^ j];
            bool  up   = ((tid & k) == 0);
            bool  iLow = ((tid & j) == 0);
            float lo = iLow ? v0 : pv, hi = iLow ? pv : v0;
            bool  sw = up ? (lo > hi) : (lo < hi);
            dvn[tid] = sw ? pv : v0;
            pmn[tid] = sw ? pi : i0;
            __syncthreads();
            float* tf = dvc; dvc = dvn; dvn = tf;
            unsigned short* tp = pmc; pmc = pmn; pmn = tp;
        }
        v = dvc[tid]; idx = pmc[tid];
#pragma unroll
        for (int j = 16; j >= 1; j >>= 1) shfl_pass(v, idx, j, k, tid);
        dvc[tid] = v; pmc[tid] = (unsigned short)idx;
        __syncthreads();
    }
    const float*          dvf = dvc;
    const unsigned short* pmf = pmc;

    // --- exps ---
    const float dmax = dvf[1023];
    float  xx = v - dmax;
    float2 ev = make_float2(__expf(xx), __expf(NEG * xx));
    gE[bh * 1024 + tid]    = ev;
    gPerm[bh * 1024 + tid] = pmf[tid];

    // --- fused inclusive block scan of (e1, e2) ---
    {
        float2 sv = ev;
#pragma unroll
        for (int off = 1; off < 32; off <<= 1) {
            float nx = __shfl_up_sync(0xFFFFFFFFu, sv.x, off);
            float ny = __shfl_up_sync(0xFFFFFFFFu, sv.y, off);
            if (lane >= off) { sv.x += nx; sv.y += ny; }
        }
        if (lane == 31) S.wsum2[wid] = sv;
        __syncthreads();
        if (wid == 0) {
            float2 w = S.wsum2[lane];
#pragma unroll
            for (int off = 1; off < 32; off <<= 1) {
                float nx = __shfl_up_sync(0xFFFFFFFFu, w.x, off);
                float ny = __shfl_up_sync(0xFFFFFFFFu, w.y, off);
                if (lane >= off) { w.x += nx; w.y += ny; }
            }
            S.wsum2[lane] = w;
        }
        __syncthreads();
        if (wid) { float2 c = S.wsum2[wid - 1]; sv.x += c.x; sv.y += c.y; }
        S.pe[tid] = sv;
        __syncthreads();
    }

    // --- binary search + per-query coefficients ---
    float c1c, c2c;
    int   kk;
    {
        const float T1 = S.pe[1023].x;
        float key = -s;
        int   k   = 0;
#pragma unroll
        for (int step = 1024; step >= 1; step >>= 1) {
            int nk = k + step;
            if (nk <= 1024 && dvf[nk - 1] < key) k = nk;
        }
        kk = k;
        float u  = s + dmax;
        float m  = fmaxf(u, NEG * u);
        float w1 = __expf(u - m);
        float w2 = __expf(NEG * u - m);
        float2 P = (k > 0) ? S.pe[k - 1] : make_float2(0.f, 0.f);
        float den = fmaf(w1, T1 - P.x, w2 * P.y);
        float inv = 1.f / den;
        c1c = w1 * inv;
        c2c = w2 * inv;
    }

    // --- counting sort of queries by bucket = k ---
    for (int i = tid; i < 1025; i += 1024) S.cnt[i] = 0;
    __syncthreads();
    atomicAdd(&S.cnt[kk], 1);
    __syncthreads();
    {
        int cv = S.cnt[tid];
#pragma unroll
        for (int off = 1; off < 32; off <<= 1) {
            int n = __shfl_up_sync(0xFFFFFFFFu, cv, off);
            if (lane >= off) cv += n;
        }
        if (lane == 31) S.wsumI[wid] = cv;
        __syncthreads();
        if (wid == 0) {
            int w = S.wsumI[lane];
#pragma unroll
            for (int off = 1; off < 32; off <<= 1) {
                int n = __shfl_up_sync(0xFFFFFFFFu, w, off);
                if (lane >= off) w += n;
            }
            S.wsumI[lane] = w;
        }
        __syncthreads();
        S.starts[tid + 1] = cv + (wid ? S.wsumI[wid - 1] : 0);
        if (tid == 0) S.starts[0] = 0;
        __syncthreads();
        if (tid == 0) S.starts[1025] = S.starts[1024] + S.cnt[1024];
        __syncthreads();
    }
    for (int i = tid; i < 1025; i += 1024) S.cnt[i] = 0;
    __syncthreads();
    {
        int pos = S.starts[kk] + atomicAdd(&S.cnt[kk], 1);
        gQC[bh * 1024 + pos]   = make_float2(c1c, c2c);
        gQOut[bh * 1024 + pos] = (unsigned short)tid;
    }
    for (int i = tid; i < 1026; i += 1024) gStarts[bh * 1026 + i] = S.starts[i];
}

// ---------------------------------------------------------------------------
// vecC: fused vector phase. 32 clusters x 4 CTAs x 256 thr. CTA rank r owns
// segments r*8..r*8+7: computes totals (rows kept in registers), broadcasts
// totals to all 4 CTAs via DSMEM, cluster-sync, offsets, merge-emit.
// Summation order identical to the 2-kernel version -> bit-identical output.
// ---------------------------------------------------------------------------
__global__ __cluster_dims__(4, 1, 1) __launch_bounds__(256)
void vecC(float* __restrict__ out) {
    __shared__ float2         sTot[32][32];     // 8 KB, written by all 4 CTAs
    __shared__ unsigned short sPm[256];
    __shared__ float2         sE[256];
    __shared__ int            sStarts[258];
    __shared__ float2         sQc[1024];
    __shared__ unsigned short sQo[1024];

    const int bh   = blockIdx.x >> 2;
    const int rank = blockIdx.x & 3;
    const int b = bh >> 2, head = bh & 3;
    const int tid = threadIdx.x, lane = tid & 31, wid = tid >> 5;
    const int base = bh * 1024 + rank * 256;

    sPm[tid] = gPerm[base + tid];
    sE[tid]  = gE[base + tid];
    for (int i = tid; i < 258; i += 256) sStarts[i] = gStarts[bh * 1026 + rank * 256 + i];
    __syncthreads();

    const int q0   = sStarts[0];
    const int qEnd = (rank == 3) ? sStarts[257] : sStarts[256];
    for (int t = tid; t < qEnd - q0; t += 256) {
        sQc[t] = gQC[bh * 1024 + q0 + t];
        sQo[t] = gQOut[bh * 1024 + q0 + t];
    }

    // --- this warp's segment: gather rows (stay in regs), compute totals ---
    const float* hhead = gH + (size_t)b * 1024 * 128 + head * 32;
    const int emitSeg = rank * 8 + wid;
    const int j0 = wid * 32;                    // local within this CTA's slice
    float hv[32];
#pragma unroll 8
    for (int jj = 0; jj < 32; jj++)
        hv[jj] = hhead[(size_t)sPm[j0 + jj] * 128 + lane];

    float t1 = 0.f, t2 = 0.f;
#pragma unroll 8
    for (int jj = 0; jj < 32; jj++) {
        float2 ee = sE[j0 + jj];
        t1 = fmaf(ee.x, hv[jj], t1);
        t2 = fmaf(ee.y, hv[jj], t2);
    }

    // --- broadcast totals to all 4 CTAs' sTot[emitSeg][lane] via DSMEM ---
    {
        uint32_t  laddr = smem_u32(&sTot[emitSeg][lane]);
        uint64_t  pack;
        asm volatile("mov.b64 %0, {%1, %2};" : "=l"(pack) : "f"(t1), "f"(t2));
#pragma unroll
        for (int r = 0; r < 4; r++) {
            uint32_t raddr;
            asm volatile("mapa.shared::cluster.u32 %0, %1, %2;"
                         : "=r"(raddr) : "r"(laddr), "r"(r));
            asm volatile("st.shared::cluster.b64 [%0], %1;"
                         :: "r"(raddr), "l"(pack) : "memory");
        }
    }
    asm volatile("barrier.cluster.arrive.aligned;" ::: "memory");
    asm volatile("barrier.cluster.wait.aligned;" ::: "memory");

    // --- offsets + grand total (same order as before) ---
    float tv1 = 0.f, off1 = 0.f, off2 = 0.f;
#pragma unroll
    for (int t = 0; t < 32; t++) {
        float2 tt = sTot[t][lane];
        tv1 += tt.x;
        if (t < emitSeg) { off1 += tt.x; off2 += tt.y; }
    }

    // --- merge-emit (modest unroll: keep body small for I$) ---
    float acc1 = off1, acc2 = off2;
    int    qp = sStarts[j0];
    float* ob = out + (size_t)(b * 1024) * 128 + head * 32 + lane;

#pragma unroll 4
    for (int jj = 0; jj < 32; jj++) {
        int qe = sStarts[j0 + jj + 1];
        while (qp < qe) {
            float2 cc = sQc[qp - q0];
            int    i  = sQo[qp - q0];
            ob[(size_t)i * 128] = fmaf(cc.x, tv1 - acc1, cc.y * acc2);
            qp++;
        }
        float2 ee = sE[j0 + jj];
        acc1 = fmaf(ee.x, hv[jj], acc1);
        acc2 = fmaf(ee.y, hv[jj], acc2);
    }
    if (emitSeg == 31) {                        // bucket k == 1024
        int qT = sStarts[257];
        while (qp < qT) {
            float2 cc = sQc[qp - q0];
            int    i  = sQo[qp - q0];
            ob[(size_t)i * 128] = fmaf(cc.x, tv1 - acc1, cc.y * acc2);
            qp++;
        }
    }
}

// ---------------------------------------------------------------------------
// Launch: fork gemm onto a side stream (concurrent with scalK), join, then
// the cluster-fused vector kernel. Stream/events created once (host-side).
// ---------------------------------------------------------------------------
extern "C" void kernel_launch(void* const* d_in, const int* in_sizes, int n_in,
                              void* d_out, int out_size) {
    const float* x     = (const float*)d_in[0];
    const float* W     = (const float*)d_in[1];
    const float* a_src = (const float*)d_in[2];
    const float* a_dst = (const float*)d_in[3];
    float*       out   = (float*)d_out;

    static cudaStream_t s2 = nullptr;
    static cudaEvent_t  evFork, evJoin;
    static int inited = 0;
    if (!inited) {
        cudaStreamCreateWithFlags(&s2, cudaStreamNonBlocking);
        cudaEventCreateWithFlags(&evFork, cudaEventDisableTiming);
        cudaEventCreateWithFlags(&evJoin, cudaEventDisableTiming);
        cudaFuncSetAttribute(scalK, cudaFuncAttributeMaxDynamicSharedMemorySize,
                             (int)sizeof(ScalS));
        inited = 1;
    }

    cudaEventRecord(evFork, 0);
    cudaStreamWaitEvent(s2, evFork, 0);
    gemm_kernel<<<dim3(128, 2), 256, 0, s2>>>(x, W);
    scalK<<<32, 1024, sizeof(ScalS)>>>(x, W, a_src, a_dst);
    cudaEventRecord(evJoin, s2);
    cudaStreamWaitEvent(0, evJoin, 0);

    vecC<<<128, 256>>>(out);
}